// round 11
// baseline (speedup 1.0000x reference)
#include <cuda_runtime.h>
#include <cuda_bf16.h>
#include <stdint.h>

#define D_DIM 128
#define T_TYPES 6
#define KT  (T_TYPES * D_DIM)            // 768
#define KDIM (KT + D_DIM)                // 896
#define LN_EPS 1e-5f
#define MAXN 50000

#define BM 64
#define BN 128
#define BK 32
#define LDA 40                            // padded bf16 row stride for A (conflict-free)

// Scratch (allocation-free rule: __device__ globals)
__device__ __align__(16) float g_sums[(size_t)MAXN * KT];      // (N,T,D) segment sums
__device__ int   g_cnt[MAXN * T_TYPES];                        // (N,T) segment counts
__device__ float g_bias[D_DIM];                                // sum_t (b[t]+emb[t])
__device__ __align__(16) __nv_bfloat16 g_Bh[D_DIM * KDIM];     // B hi, n-major [128][896]
__device__ __align__(16) __nv_bfloat16 g_Bl[D_DIM * KDIM];     // B lo, n-major

// ---------------------------------------------------------------------------
__global__ void zero_kernel(int n_nodes) {
    size_t stride = (size_t)gridDim.x * blockDim.x;
    size_t base = (size_t)blockIdx.x * blockDim.x + threadIdx.x;
    size_t tot4 = (size_t)n_nodes * KT / 4;
    float4 z = make_float4(0.f, 0.f, 0.f, 0.f);
    for (size_t i = base; i < tot4; i += stride)
        reinterpret_cast<float4*>(g_sums)[i] = z;
    size_t nt = (size_t)n_nodes * T_TYPES;
    for (size_t i = base; i < nt; i += stride)
        g_cnt[i] = 0;
}

// ---------------------------------------------------------------------------
__global__ void prep_b_kernel(const float* __restrict__ Wl,
                              const float* __restrict__ Wr,
                              const float* __restrict__ b,
                              const float* __restrict__ emb) {
    int idx = blockIdx.x * blockDim.x + threadIdx.x;
    if (idx < D_DIM * KDIM) {
        int o = idx / KDIM;
        int k = idx % KDIM;
        float w;
        if (k < KT) {
            w = Wl[(size_t)k * D_DIM + o];
        } else {
            int d = k - KT;
            float s = 0.f;
            #pragma unroll
            for (int t = 0; t < T_TYPES; t++)
                s += Wr[(size_t)t * D_DIM * D_DIM + d * D_DIM + o];
            w = s;
        }
        __nv_bfloat16 hi = __float2bfloat16(w);
        __nv_bfloat16 lo = __float2bfloat16(w - __bfloat162float(hi));
        g_Bh[idx] = hi;
        g_Bl[idx] = lo;
    }
    if (idx < D_DIM) {
        float s = 0.f;
        #pragma unroll
        for (int t = 0; t < T_TYPES; t++)
            s += b[t * D_DIM + idx] + emb[t * D_DIM + idx];
        g_bias[idx] = s;
    }
}

// ---------------------------------------------------------------------------
__global__ __launch_bounds__(256) void scatter_kernel(
    const float* __restrict__ x,
    const int* __restrict__ ei,   // (2,E) int32
    const int* __restrict__ et,   // (E,)  int32
    int E)
{
    int w = (int)(((size_t)blockIdx.x * blockDim.x + threadIdx.x) >> 5);
    int lane = threadIdx.x & 31;
    if (w >= E) return;

    int src = ei[w];
    int dst = ei[E + w];
    int ty  = et[w];

    float4 xv = reinterpret_cast<const float4*>(x + (size_t)src * D_DIM)[lane];
    float4* dp = reinterpret_cast<float4*>(
        g_sums + ((size_t)dst * T_TYPES + (size_t)ty) * D_DIM) + lane;
    atomicAdd(dp, xv);
    if (lane == 0)
        atomicAdd(&g_cnt[dst * T_TYPES + ty], 1);
}

// ---------------------------------------------------------------------------
// cp.async helpers
// ---------------------------------------------------------------------------
__device__ __forceinline__ void cp_async16(void* dst_smem, const void* src) {
    uint32_t d = (uint32_t)__cvta_generic_to_shared(dst_smem);
    asm volatile("cp.async.cg.shared.global [%0], [%1], 16;\n" :: "r"(d), "l"(src));
}
#define CP_COMMIT() asm volatile("cp.async.commit_group;\n" ::: "memory")
#define CP_WAIT(n)  asm volatile("cp.async.wait_group %0;\n" :: "n"(n) : "memory")

__device__ __forceinline__ void mma16816(float* c, const uint32_t* a,
                                         uint32_t b0, uint32_t b1) {
    asm volatile(
        "mma.sync.aligned.m16n8k16.row.col.f32.bf16.bf16.f32 "
        "{%0,%1,%2,%3}, {%4,%5,%6,%7}, {%8,%9}, {%0,%1,%2,%3};\n"
        : "+f"(c[0]), "+f"(c[1]), "+f"(c[2]), "+f"(c[3])
        : "r"(a[0]), "r"(a[1]), "r"(a[2]), "r"(a[3]), "r"(b0), "r"(b1));
}

// B smem: LDA=32 (64B rows), chunk-XOR swizzle for conflict-free LDS + 16B cp.async.
// logical (n, k[bf16]) -> byte offset within one 8KB B matrix
__device__ __forceinline__ uint32_t bofs(int n, int k) {
    return (uint32_t)(n * 64 + ((((k >> 3) ^ ((n >> 1) & 3)) << 4)) + ((k & 7) << 1));
}

// ---------------------------------------------------------------------------
// Split-bf16 tensor-core GEMM + bias + LayerNorm + ReLU, pipelined.
// Block 64x128, BK=32, 8 warps (4m x 2n), warp tile 16x64, mma.m16n8k16.
// B: cp.async double-buffered (2 stages).  A: register-prefetched LDG,
// fp32->bf16 hi/lo split at STS time (single-stage smem).
// ---------------------------------------------------------------------------
__global__ __launch_bounds__(256, 2) void gemm_ln_kernel(
    const float* __restrict__ x,
    const float* __restrict__ gamma, const float* __restrict__ beta,
    float* __restrict__ out, int n_nodes)
{
    __shared__ __align__(16) __nv_bfloat16 sAh[BM * LDA];   // 5120 B
    __shared__ __align__(16) __nv_bfloat16 sAl[BM * LDA];   // 5120 B
    __shared__ __align__(16) char sB[2 * 2 * 8192];         // [stage][hi/lo][128][32] 32768 B
    __shared__ float sRed[BM * 4];                          // 1024 B

    const int tid   = threadIdx.x;
    const int warp  = tid >> 5;
    const int lane  = tid & 31;
    const int g     = lane >> 2;          // 0..7
    const int q     = lane & 3;           // 0..3
    const int warpM = warp & 3;           // rows warpM*16
    const int warpN = warp >> 2;          // cols warpN*64
    const int n0    = blockIdx.x * BM;

    // A loader coords (2 float4 per thread per tile)
    const int arow0 = tid >> 3;            // rows 0..31  (it=0)
    const int arow1 = (tid + 256) >> 3;    // rows 32..63 (it=1)
    const int akq   = tid & 7;             // float4 index in row

    float acc[8][4];
    #pragma unroll
    for (int ni = 0; ni < 8; ni++)
        #pragma unroll
        for (int c = 0; c < 4; c++) acc[ni][c] = 0.f;

    float4 aPre[2];

    // ---- A global load for tile kt into registers ----
    auto loadA = [&](int kt, float4* dstv) {
        const int k0 = kt * BK;
        #pragma unroll
        for (int it = 0; it < 2; it++) {
            int row = it == 0 ? arow0 : arow1;
            int n = n0 + row;
            float4 v = make_float4(0.f, 0.f, 0.f, 0.f);
            if (n < n_nodes) {
                if (k0 < KT) {
                    v = reinterpret_cast<const float4*>(
                            g_sums + (size_t)n * KT + k0)[akq];
                    int c = g_cnt[n * T_TYPES + (k0 >> 7)];
                    float s = 1.f / fmaxf((float)c, 1.f);
                    v.x *= s; v.y *= s; v.z *= s; v.w *= s;
                } else {
                    v = reinterpret_cast<const float4*>(
                            x + (size_t)n * D_DIM + (k0 - KT))[akq];
                }
            }
            dstv[it] = v;
        }
    };

    // ---- B cp.async for tile kt into stage ----
    auto loadB = [&](int kt) {
        const int k0 = kt * BK;
        char* stageBase = sB + (kt & 1) * 16384;
        #pragma unroll
        for (int it = 0; it < 2; it++) {
            int idx = tid + it * 256;     // 0..511
            int n = idx >> 2;
            int j = idx & 3;
            uint32_t doff = (uint32_t)(n * 64 + ((j ^ ((n >> 1) & 3)) << 4));
            cp_async16(stageBase + doff,          g_Bh + (size_t)n * KDIM + k0 + j * 8);
            cp_async16(stageBase + 8192 + doff,   g_Bl + (size_t)n * KDIM + k0 + j * 8);
        }
        CP_COMMIT();
    };

    // prologue
    loadA(0, aPre);
    loadB(0);

    for (int kt = 0; kt < KDIM / BK; kt++) {
        // STS A (sA free: all warps synced after previous compute)
        #pragma unroll
        for (int it = 0; it < 2; it++) {
            int row = it == 0 ? arow0 : arow1;
            float4 v = aPre[it];
            __nv_bfloat16 h0 = __float2bfloat16(v.x);
            __nv_bfloat16 h1 = __float2bfloat16(v.y);
            __nv_bfloat16 h2 = __float2bfloat16(v.z);
            __nv_bfloat16 h3 = __float2bfloat16(v.w);
            __nv_bfloat16 l0 = __float2bfloat16(v.x - __bfloat162float(h0));
            __nv_bfloat16 l1 = __float2bfloat16(v.y - __bfloat162float(h1));
            __nv_bfloat16 l2 = __float2bfloat16(v.z - __bfloat162float(h2));
            __nv_bfloat16 l3 = __float2bfloat16(v.w - __bfloat162float(h3));
            int off = row * LDA + akq * 4;
            *reinterpret_cast<__nv_bfloat162*>(&sAh[off])     = __nv_bfloat162(h0, h1);
            *reinterpret_cast<__nv_bfloat162*>(&sAh[off + 2]) = __nv_bfloat162(h2, h3);
            *reinterpret_cast<__nv_bfloat162*>(&sAl[off])     = __nv_bfloat162(l0, l1);
            *reinterpret_cast<__nv_bfloat162*>(&sAl[off + 2]) = __nv_bfloat162(l2, l3);
        }
        // prefetch next tile
        if (kt + 1 < KDIM / BK) {
            loadA(kt + 1, aPre);
            loadB(kt + 1);
            CP_WAIT(1);           // tile kt's B group complete
        } else {
            CP_WAIT(0);
        }
        __syncthreads();

        const char* bh = sB + (kt & 1) * 16384;
        const char* bl = bh + 8192;

        #pragma unroll
        for (int ks = 0; ks < 2; ks++) {
            const int kb = ks * 16 + q * 2;
            const int r = warpM * 16 + g;
            uint32_t ah[4], al[4];
            ah[0] = *reinterpret_cast<const uint32_t*>(&sAh[r * LDA + kb]);
            ah[1] = *reinterpret_cast<const uint32_t*>(&sAh[(r + 8) * LDA + kb]);
            ah[2] = *reinterpret_cast<const uint32_t*>(&sAh[r * LDA + kb + 8]);
            ah[3] = *reinterpret_cast<const uint32_t*>(&sAh[(r + 8) * LDA + kb + 8]);
            al[0] = *reinterpret_cast<const uint32_t*>(&sAl[r * LDA + kb]);
            al[1] = *reinterpret_cast<const uint32_t*>(&sAl[(r + 8) * LDA + kb]);
            al[2] = *reinterpret_cast<const uint32_t*>(&sAl[r * LDA + kb + 8]);
            al[3] = *reinterpret_cast<const uint32_t*>(&sAl[(r + 8) * LDA + kb + 8]);
            #pragma unroll
            for (int ni = 0; ni < 8; ni++) {
                int n = warpN * 64 + ni * 8 + g;
                uint32_t bh0 = *reinterpret_cast<const uint32_t*>(bh + bofs(n, kb));
                uint32_t bh1 = *reinterpret_cast<const uint32_t*>(bh + bofs(n, kb + 8));
                uint32_t bl0 = *reinterpret_cast<const uint32_t*>(bl + bofs(n, kb));
                uint32_t bl1 = *reinterpret_cast<const uint32_t*>(bl + bofs(n, kb + 8));
                mma16816(acc[ni], ah, bh0, bh1);
                mma16816(acc[ni], ah, bl0, bl1);
                mma16816(acc[ni], al, bh0, bh1);
            }
        }
        __syncthreads();
    }

    // ---- bias ----
    float2 bias2[8], gam2[8], bet2[8];
    #pragma unroll
    for (int ni = 0; ni < 8; ni++) {
        int col = warpN * 64 + ni * 8 + q * 2;
        bias2[ni] = *reinterpret_cast<const float2*>(&g_bias[col]);
        gam2[ni]  = *reinterpret_cast<const float2*>(&gamma[col]);
        bet2[ni]  = *reinterpret_cast<const float2*>(&beta[col]);
    }
    #pragma unroll
    for (int ni = 0; ni < 8; ni++) {
        acc[ni][0] += bias2[ni].x;
        acc[ni][1] += bias2[ni].y;
        acc[ni][2] += bias2[ni].x;
        acc[ni][3] += bias2[ni].y;
    }

    // ---- per-row partial sums over this warp's 64 cols ----
    #pragma unroll
    for (int h = 0; h < 2; h++) {
        float s = 0.f, sq = 0.f;
        #pragma unroll
        for (int ni = 0; ni < 8; ni++) {
            float v0 = acc[ni][h * 2], v1 = acc[ni][h * 2 + 1];
            s  += v0 + v1;
            sq += v0 * v0 + v1 * v1;
        }
        s  += __shfl_xor_sync(0xffffffffu, s, 1);
        s  += __shfl_xor_sync(0xffffffffu, s, 2);
        sq += __shfl_xor_sync(0xffffffffu, sq, 1);
        sq += __shfl_xor_sync(0xffffffffu, sq, 2);
        if (q == 0) {
            int r = warpM * 16 + g + h * 8;
            sRed[r * 4 + warpN]     = s;
            sRed[r * 4 + 2 + warpN] = sq;
        }
    }
    __syncthreads();

    // ---- LN + ReLU + store ----
    #pragma unroll
    for (int h = 0; h < 2; h++) {
        int r = warpM * 16 + g + h * 8;
        int n = n0 + r;
        float S  = sRed[r * 4]     + sRed[r * 4 + 1];
        float Q  = sRed[r * 4 + 2] + sRed[r * 4 + 3];
        float mean = S * (1.f / 128.f);
        float var  = Q * (1.f / 128.f) - mean * mean;
        float rstd = rsqrtf(var + LN_EPS);
        if (n < n_nodes) {
            #pragma unroll
            for (int ni = 0; ni < 8; ni++) {
                int col = warpN * 64 + ni * 8 + q * 2;
                float v0 = acc[ni][h * 2], v1 = acc[ni][h * 2 + 1];
                float y0 = fmaxf((v0 - mean) * rstd * gam2[ni].x + bet2[ni].x, 0.f);
                float y1 = fmaxf((v1 - mean) * rstd * gam2[ni].y + bet2[ni].y, 0.f);
                *reinterpret_cast<float2*>(&out[(size_t)n * D_DIM + col]) =
                    make_float2(y0, y1);
            }
        }
    }
}

// ---------------------------------------------------------------------------
extern "C" void kernel_launch(void* const* d_in, const int* in_sizes, int n_in,
                              void* d_out, int out_size) {
    const float* x     = (const float*)d_in[0];
    const int*   ei    = (const int*)d_in[1];   // int32 (JAX x64 off)
    const int*   et    = (const int*)d_in[2];   // int32
    const float* Wl    = (const float*)d_in[3];
    const float* Wr    = (const float*)d_in[4];
    const float* b     = (const float*)d_in[5];
    const float* emb   = (const float*)d_in[6];
    const float* gamma = (const float*)d_in[7];
    const float* beta  = (const float*)d_in[8];
    float* out = (float*)d_out;

    int n_nodes = in_sizes[0] / D_DIM;
    int E       = in_sizes[2];

    zero_kernel<<<2048, 256>>>(n_nodes);
    prep_b_kernel<<<(D_DIM * KDIM + 255) / 256, 256>>>(Wl, Wr, b, emb);
    scatter_kernel<<<(E + 7) / 8, 256>>>(x, ei, et, E);
    gemm_ln_kernel<<<(n_nodes + BM - 1) / BM, 256>>>(x, gamma, beta, out, n_nodes);
}

// round 12
// speedup vs baseline: 1.0118x; 1.0118x over previous
#include <cuda_runtime.h>
#include <cuda_bf16.h>
#include <stdint.h>

#define D_DIM 128
#define T_TYPES 6
#define KT  (T_TYPES * D_DIM)            // 768
#define KDIM (KT + D_DIM)                // 896
#define LN_EPS 1e-5f
#define MAXN 50000

#define BM 64
#define BN 128
#define BK 32
#define LDA 40                            // padded bf16 row stride for A (conflict-free)

// Scratch (allocation-free rule: __device__ globals)
__device__ __align__(16) float g_sums[(size_t)MAXN * KT];      // (N,T,D) segment sums
__device__ int   g_cnt[MAXN * T_TYPES];                        // (N,T) segment counts
__device__ float g_bias[D_DIM];                                // sum_t (b[t]+emb[t])
__device__ __align__(16) __nv_bfloat16 g_Bh[D_DIM * KDIM];     // B hi, n-major [128][896]
__device__ __align__(16) __nv_bfloat16 g_Bl[D_DIM * KDIM];     // B lo, n-major

// ---------------------------------------------------------------------------
__global__ void zero_kernel(int n_nodes) {
    size_t stride = (size_t)gridDim.x * blockDim.x;
    size_t base = (size_t)blockIdx.x * blockDim.x + threadIdx.x;
    size_t tot4 = (size_t)n_nodes * KT / 4;
    float4 z = make_float4(0.f, 0.f, 0.f, 0.f);
    for (size_t i = base; i < tot4; i += stride)
        reinterpret_cast<float4*>(g_sums)[i] = z;
    size_t nt = (size_t)n_nodes * T_TYPES;
    for (size_t i = base; i < nt; i += stride)
        g_cnt[i] = 0;
}

// ---------------------------------------------------------------------------
__global__ void prep_b_kernel(const float* __restrict__ Wl,
                              const float* __restrict__ Wr,
                              const float* __restrict__ b,
                              const float* __restrict__ emb) {
    int idx = blockIdx.x * blockDim.x + threadIdx.x;
    if (idx < D_DIM * KDIM) {
        int o = idx / KDIM;
        int k = idx % KDIM;
        float w;
        if (k < KT) {
            w = Wl[(size_t)k * D_DIM + o];
        } else {
            int d = k - KT;
            float s = 0.f;
            #pragma unroll
            for (int t = 0; t < T_TYPES; t++)
                s += Wr[(size_t)t * D_DIM * D_DIM + d * D_DIM + o];
            w = s;
        }
        __nv_bfloat16 hi = __float2bfloat16(w);
        __nv_bfloat16 lo = __float2bfloat16(w - __bfloat162float(hi));
        g_Bh[idx] = hi;
        g_Bl[idx] = lo;
    }
    if (idx < D_DIM) {
        float s = 0.f;
        #pragma unroll
        for (int t = 0; t < T_TYPES; t++)
            s += b[t * D_DIM + idx] + emb[t * D_DIM + idx];
        g_bias[idx] = s;
    }
}

// ---------------------------------------------------------------------------
__global__ __launch_bounds__(256) void scatter_kernel(
    const float* __restrict__ x,
    const int* __restrict__ ei,   // (2,E) int32
    const int* __restrict__ et,   // (E,)  int32
    int E)
{
    int w = (int)(((size_t)blockIdx.x * blockDim.x + threadIdx.x) >> 5);
    int lane = threadIdx.x & 31;
    if (w >= E) return;

    int src = ei[w];
    int dst = ei[E + w];
    int ty  = et[w];

    float4 xv = reinterpret_cast<const float4*>(x + (size_t)src * D_DIM)[lane];
    float4* dp = reinterpret_cast<float4*>(
        g_sums + ((size_t)dst * T_TYPES + (size_t)ty) * D_DIM) + lane;
    atomicAdd(dp, xv);
    if (lane == 0)
        atomicAdd(&g_cnt[dst * T_TYPES + ty], 1);
}

// ---------------------------------------------------------------------------
// cp.async helpers
// ---------------------------------------------------------------------------
__device__ __forceinline__ void cp_async16(void* dst_smem, const void* src) {
    uint32_t d = (uint32_t)__cvta_generic_to_shared(dst_smem);
    asm volatile("cp.async.cg.shared.global [%0], [%1], 16;\n" :: "r"(d), "l"(src));
}
#define CP_COMMIT() asm volatile("cp.async.commit_group;\n" ::: "memory")
#define CP_WAIT(n)  asm volatile("cp.async.wait_group %0;\n" :: "n"(n) : "memory")

__device__ __forceinline__ void mma16816(float* c, const uint32_t* a,
                                         uint32_t b0, uint32_t b1) {
    asm volatile(
        "mma.sync.aligned.m16n8k16.row.col.f32.bf16.bf16.f32 "
        "{%0,%1,%2,%3}, {%4,%5,%6,%7}, {%8,%9}, {%0,%1,%2,%3};\n"
        : "+f"(c[0]), "+f"(c[1]), "+f"(c[2]), "+f"(c[3])
        : "r"(a[0]), "r"(a[1]), "r"(a[2]), "r"(a[3]), "r"(b0), "r"(b1));
}

// B smem: LDA=32 (64B rows), chunk-XOR swizzle for conflict-free LDS + 16B cp.async.
// logical (n, k[bf16]) -> byte offset within one 8KB B matrix
__device__ __forceinline__ uint32_t bofs(int n, int k) {
    return (uint32_t)(n * 64 + ((((k >> 3) ^ ((n >> 1) & 3)) << 4)) + ((k & 7) << 1));
}

// ---------------------------------------------------------------------------
// Split-bf16 tensor-core GEMM + bias + LayerNorm + ReLU, pipelined.
// Block 64x128, BK=32, 8 warps (4m x 2n), warp tile 16x64, mma.m16n8k16.
// B: cp.async double-buffered (2 stages).  A: register-prefetched LDG,
// fp32->bf16 hi/lo split at STS time (single-stage smem).
// ---------------------------------------------------------------------------
__global__ __launch_bounds__(256, 2) void gemm_ln_kernel(
    const float* __restrict__ x,
    const float* __restrict__ gamma, const float* __restrict__ beta,
    float* __restrict__ out, int n_nodes)
{
    __shared__ __align__(16) __nv_bfloat16 sAh[BM * LDA];   // 5120 B
    __shared__ __align__(16) __nv_bfloat16 sAl[BM * LDA];   // 5120 B
    __shared__ __align__(16) char sB[2 * 2 * 8192];         // [stage][hi/lo][128][32] 32768 B
    __shared__ float sRed[BM * 4];                          // 1024 B

    const int tid   = threadIdx.x;
    const int warp  = tid >> 5;
    const int lane  = tid & 31;
    const int g     = lane >> 2;          // 0..7
    const int q     = lane & 3;           // 0..3
    const int warpM = warp & 3;           // rows warpM*16
    const int warpN = warp >> 2;          // cols warpN*64
    const int n0    = blockIdx.x * BM;

    // A loader coords (2 float4 per thread per tile)
    const int arow0 = tid >> 3;            // rows 0..31  (it=0)
    const int arow1 = (tid + 256) >> 3;    // rows 32..63 (it=1)
    const int akq   = tid & 7;             // float4 index in row

    float acc[8][4];
    #pragma unroll
    for (int ni = 0; ni < 8; ni++)
        #pragma unroll
        for (int c = 0; c < 4; c++) acc[ni][c] = 0.f;

    float4 aPre[2];

    // ---- A global load for tile kt into registers ----
    auto loadA = [&](int kt, float4* dstv) {
        const int k0 = kt * BK;
        #pragma unroll
        for (int it = 0; it < 2; it++) {
            int row = it == 0 ? arow0 : arow1;
            int n = n0 + row;
            float4 v = make_float4(0.f, 0.f, 0.f, 0.f);
            if (n < n_nodes) {
                if (k0 < KT) {
                    v = reinterpret_cast<const float4*>(
                            g_sums + (size_t)n * KT + k0)[akq];
                    int c = g_cnt[n * T_TYPES + (k0 >> 7)];
                    float s = 1.f / fmaxf((float)c, 1.f);
                    v.x *= s; v.y *= s; v.z *= s; v.w *= s;
                } else {
                    v = reinterpret_cast<const float4*>(
                            x + (size_t)n * D_DIM + (k0 - KT))[akq];
                }
            }
            dstv[it] = v;
        }
    };

    // ---- B cp.async for tile kt into stage ----
    auto loadB = [&](int kt) {
        const int k0 = kt * BK;
        char* stageBase = sB + (kt & 1) * 16384;
        #pragma unroll
        for (int it = 0; it < 2; it++) {
            int idx = tid + it * 256;     // 0..511
            int n = idx >> 2;
            int j = idx & 3;
            uint32_t doff = (uint32_t)(n * 64 + ((j ^ ((n >> 1) & 3)) << 4));
            cp_async16(stageBase + doff,          g_Bh + (size_t)n * KDIM + k0 + j * 8);
            cp_async16(stageBase + 8192 + doff,   g_Bl + (size_t)n * KDIM + k0 + j * 8);
        }
        CP_COMMIT();
    };

    // prologue
    loadA(0, aPre);
    loadB(0);

    for (int kt = 0; kt < KDIM / BK; kt++) {
        // STS A (sA free: all warps synced after previous compute)
        #pragma unroll
        for (int it = 0; it < 2; it++) {
            int row = it == 0 ? arow0 : arow1;
            float4 v = aPre[it];
            __nv_bfloat16 h0 = __float2bfloat16(v.x);
            __nv_bfloat16 h1 = __float2bfloat16(v.y);
            __nv_bfloat16 h2 = __float2bfloat16(v.z);
            __nv_bfloat16 h3 = __float2bfloat16(v.w);
            __nv_bfloat16 l0 = __float2bfloat16(v.x - __bfloat162float(h0));
            __nv_bfloat16 l1 = __float2bfloat16(v.y - __bfloat162float(h1));
            __nv_bfloat16 l2 = __float2bfloat16(v.z - __bfloat162float(h2));
            __nv_bfloat16 l3 = __float2bfloat16(v.w - __bfloat162float(h3));
            int off = row * LDA + akq * 4;
            *reinterpret_cast<__nv_bfloat162*>(&sAh[off])     = __nv_bfloat162(h0, h1);
            *reinterpret_cast<__nv_bfloat162*>(&sAh[off + 2]) = __nv_bfloat162(h2, h3);
            *reinterpret_cast<__nv_bfloat162*>(&sAl[off])     = __nv_bfloat162(l0, l1);
            *reinterpret_cast<__nv_bfloat162*>(&sAl[off + 2]) = __nv_bfloat162(l2, l3);
        }
        // prefetch next tile
        if (kt + 1 < KDIM / BK) {
            loadA(kt + 1, aPre);
            loadB(kt + 1);
            CP_WAIT(1);           // tile kt's B group complete
        } else {
            CP_WAIT(0);
        }
        __syncthreads();

        const char* bh = sB + (kt & 1) * 16384;
        const char* bl = bh + 8192;

        #pragma unroll
        for (int ks = 0; ks < 2; ks++) {
            const int kb = ks * 16 + q * 2;
            const int r = warpM * 16 + g;
            uint32_t ah[4], al[4];
            ah[0] = *reinterpret_cast<const uint32_t*>(&sAh[r * LDA + kb]);
            ah[1] = *reinterpret_cast<const uint32_t*>(&sAh[(r + 8) * LDA + kb]);
            ah[2] = *reinterpret_cast<const uint32_t*>(&sAh[r * LDA + kb + 8]);
            ah[3] = *reinterpret_cast<const uint32_t*>(&sAh[(r + 8) * LDA + kb + 8]);
            al[0] = *reinterpret_cast<const uint32_t*>(&sAl[r * LDA + kb]);
            al[1] = *reinterpret_cast<const uint32_t*>(&sAl[(r + 8) * LDA + kb]);
            al[2] = *reinterpret_cast<const uint32_t*>(&sAl[r * LDA + kb + 8]);
            al[3] = *reinterpret_cast<const uint32_t*>(&sAl[(r + 8) * LDA + kb + 8]);
            #pragma unroll
            for (int ni = 0; ni < 8; ni++) {
                int n = warpN * 64 + ni * 8 + g;
                uint32_t bh0 = *reinterpret_cast<const uint32_t*>(bh + bofs(n, kb));
                uint32_t bh1 = *reinterpret_cast<const uint32_t*>(bh + bofs(n, kb + 8));
                uint32_t bl0 = *reinterpret_cast<const uint32_t*>(bl + bofs(n, kb));
                uint32_t bl1 = *reinterpret_cast<const uint32_t*>(bl + bofs(n, kb + 8));
                mma16816(acc[ni], ah, bh0, bh1);
                mma16816(acc[ni], ah, bl0, bl1);
                mma16816(acc[ni], al, bh0, bh1);
            }
        }
        __syncthreads();
    }

    // ---- bias ----
    float2 bias2[8], gam2[8], bet2[8];
    #pragma unroll
    for (int ni = 0; ni < 8; ni++) {
        int col = warpN * 64 + ni * 8 + q * 2;
        bias2[ni] = *reinterpret_cast<const float2*>(&g_bias[col]);
        gam2[ni]  = *reinterpret_cast<const float2*>(&gamma[col]);
        bet2[ni]  = *reinterpret_cast<const float2*>(&beta[col]);
    }
    #pragma unroll
    for (int ni = 0; ni < 8; ni++) {
        acc[ni][0] += bias2[ni].x;
        acc[ni][1] += bias2[ni].y;
        acc[ni][2] += bias2[ni].x;
        acc[ni][3] += bias2[ni].y;
    }

    // ---- per-row partial sums over this warp's 64 cols ----
    #pragma unroll
    for (int h = 0; h < 2; h++) {
        float s = 0.f, sq = 0.f;
        #pragma unroll
        for (int ni = 0; ni < 8; ni++) {
            float v0 = acc[ni][h * 2], v1 = acc[ni][h * 2 + 1];
            s  += v0 + v1;
            sq += v0 * v0 + v1 * v1;
        }
        s  += __shfl_xor_sync(0xffffffffu, s, 1);
        s  += __shfl_xor_sync(0xffffffffu, s, 2);
        sq += __shfl_xor_sync(0xffffffffu, sq, 1);
        sq += __shfl_xor_sync(0xffffffffu, sq, 2);
        if (q == 0) {
            int r = warpM * 16 + g + h * 8;
            sRed[r * 4 + warpN]     = s;
            sRed[r * 4 + 2 + warpN] = sq;
        }
    }
    __syncthreads();

    // ---- LN + ReLU + store ----
    #pragma unroll
    for (int h = 0; h < 2; h++) {
        int r = warpM * 16 + g + h * 8;
        int n = n0 + r;
        float S  = sRed[r * 4]     + sRed[r * 4 + 1];
        float Q  = sRed[r * 4 + 2] + sRed[r * 4 + 3];
        float mean = S * (1.f / 128.f);
        float var  = Q * (1.f / 128.f) - mean * mean;
        float rstd = rsqrtf(var + LN_EPS);
        if (n < n_nodes) {
            #pragma unroll
            for (int ni = 0; ni < 8; ni++) {
                int col = warpN * 64 + ni * 8 + q * 2;
                float v0 = acc[ni][h * 2], v1 = acc[ni][h * 2 + 1];
                float y0 = fmaxf((v0 - mean) * rstd * gam2[ni].x + bet2[ni].x, 0.f);
                float y1 = fmaxf((v1 - mean) * rstd * gam2[ni].y + bet2[ni].y, 0.f);
                *reinterpret_cast<float2*>(&out[(size_t)n * D_DIM + col]) =
                    make_float2(y0, y1);
            }
        }
    }
}

// ---------------------------------------------------------------------------
extern "C" void kernel_launch(void* const* d_in, const int* in_sizes, int n_in,
                              void* d_out, int out_size) {
    const float* x     = (const float*)d_in[0];
    const int*   ei    = (const int*)d_in[1];   // int32 (JAX x64 off)
    const int*   et    = (const int*)d_in[2];   // int32
    const float* Wl    = (const float*)d_in[3];
    const float* Wr    = (const float*)d_in[4];
    const float* b     = (const float*)d_in[5];
    const float* emb   = (const float*)d_in[6];
    const float* gamma = (const float*)d_in[7];
    const float* beta  = (const float*)d_in[8];
    float* out = (float*)d_out;

    int n_nodes = in_sizes[0] / D_DIM;
    int E       = in_sizes[2];

    zero_kernel<<<2048, 256>>>(n_nodes);
    prep_b_kernel<<<(D_DIM * KDIM + 255) / 256, 256>>>(Wl, Wr, b, emb);
    scatter_kernel<<<(E + 7) / 8, 256>>>(x, ei, et, E);
    gemm_ln_kernel<<<(n_nodes + BM - 1) / BM, 256>>>(x, gamma, beta, out, n_nodes);
}

// round 13
// speedup vs baseline: 1.0131x; 1.0012x over previous
#include <cuda_runtime.h>
#include <cuda_bf16.h>
#include <stdint.h>

#define D_DIM 128
#define T_TYPES 6
#define KT  (T_TYPES * D_DIM)            // 768
#define KDIM (KT + D_DIM)                // 896
#define LN_EPS 1e-5f
#define MAXN 50000

#define BM 64
#define BN 128
#define BK 32
#define LDA 40                            // padded bf16 row stride for A (conflict-free)

// Scratch (allocation-free rule: __device__ globals)
__device__ __align__(16) float g_sums[(size_t)MAXN * KT];      // (N,T,D) segment sums
__device__ int   g_cnt[MAXN * T_TYPES];                        // (N,T) segment counts
__device__ float g_bias[D_DIM];                                // sum_t (b[t]+emb[t])
__device__ __align__(16) __nv_bfloat16 g_Bh[D_DIM * KDIM];     // B hi, n-major [128][896]
__device__ __align__(16) __nv_bfloat16 g_Bl[D_DIM * KDIM];     // B lo, n-major

// ---------------------------------------------------------------------------
__global__ void zero_kernel(int n_nodes) {
    size_t stride = (size_t)gridDim.x * blockDim.x;
    size_t base = (size_t)blockIdx.x * blockDim.x + threadIdx.x;
    size_t tot4 = (size_t)n_nodes * KT / 4;
    float4 z = make_float4(0.f, 0.f, 0.f, 0.f);
    for (size_t i = base; i < tot4; i += stride)
        reinterpret_cast<float4*>(g_sums)[i] = z;
    size_t nt = (size_t)n_nodes * T_TYPES;
    for (size_t i = base; i < nt; i += stride)
        g_cnt[i] = 0;
}

// ---------------------------------------------------------------------------
__global__ void prep_b_kernel(const float* __restrict__ Wl,
                              const float* __restrict__ Wr,
                              const float* __restrict__ b,
                              const float* __restrict__ emb) {
    int idx = blockIdx.x * blockDim.x + threadIdx.x;
    if (idx < D_DIM * KDIM) {
        int o = idx / KDIM;
        int k = idx % KDIM;
        float w;
        if (k < KT) {
            w = Wl[(size_t)k * D_DIM + o];
        } else {
            int d = k - KT;
            float s = 0.f;
            #pragma unroll
            for (int t = 0; t < T_TYPES; t++)
                s += Wr[(size_t)t * D_DIM * D_DIM + d * D_DIM + o];
            w = s;
        }
        __nv_bfloat16 hi = __float2bfloat16(w);
        __nv_bfloat16 lo = __float2bfloat16(w - __bfloat162float(hi));
        g_Bh[idx] = hi;
        g_Bl[idx] = lo;
    }
    if (idx < D_DIM) {
        float s = 0.f;
        #pragma unroll
        for (int t = 0; t < T_TYPES; t++)
            s += b[t * D_DIM + idx] + emb[t * D_DIM + idx];
        g_bias[idx] = s;
    }
}

// ---------------------------------------------------------------------------
__global__ __launch_bounds__(256) void scatter_kernel(
    const float* __restrict__ x,
    const int* __restrict__ ei,   // (2,E) int32
    const int* __restrict__ et,   // (E,)  int32
    int E)
{
    int w = (int)(((size_t)blockIdx.x * blockDim.x + threadIdx.x) >> 5);
    int lane = threadIdx.x & 31;
    if (w >= E) return;

    int src = ei[w];
    int dst = ei[E + w];
    int ty  = et[w];

    float4 xv = reinterpret_cast<const float4*>(x + (size_t)src * D_DIM)[lane];
    float4* dp = reinterpret_cast<float4*>(
        g_sums + ((size_t)dst * T_TYPES + (size_t)ty) * D_DIM) + lane;
    atomicAdd(dp, xv);
    if (lane == 0)
        atomicAdd(&g_cnt[dst * T_TYPES + ty], 1);
}

// ---------------------------------------------------------------------------
// cp.async helpers
// ---------------------------------------------------------------------------
__device__ __forceinline__ void cp_async16(void* dst_smem, const void* src) {
    uint32_t d = (uint32_t)__cvta_generic_to_shared(dst_smem);
    asm volatile("cp.async.cg.shared.global [%0], [%1], 16;\n" :: "r"(d), "l"(src));
}
#define CP_COMMIT() asm volatile("cp.async.commit_group;\n" ::: "memory")
#define CP_WAIT(n)  asm volatile("cp.async.wait_group %0;\n" :: "n"(n) : "memory")

__device__ __forceinline__ void mma16816(float* c, const uint32_t* a,
                                         uint32_t b0, uint32_t b1) {
    asm volatile(
        "mma.sync.aligned.m16n8k16.row.col.f32.bf16.bf16.f32 "
        "{%0,%1,%2,%3}, {%4,%5,%6,%7}, {%8,%9}, {%0,%1,%2,%3};\n"
        : "+f"(c[0]), "+f"(c[1]), "+f"(c[2]), "+f"(c[3])
        : "r"(a[0]), "r"(a[1]), "r"(a[2]), "r"(a[3]), "r"(b0), "r"(b1));
}

// B smem: LDA=32 (64B rows), chunk-XOR swizzle for conflict-free LDS + 16B cp.async.
// logical (n, k[bf16]) -> byte offset within one 8KB B matrix
__device__ __forceinline__ uint32_t bofs(int n, int k) {
    return (uint32_t)(n * 64 + ((((k >> 3) ^ ((n >> 1) & 3)) << 4)) + ((k & 7) << 1));
}

// ---------------------------------------------------------------------------
// Split-bf16 tensor-core GEMM + bias + LayerNorm + ReLU, pipelined.
// Block 64x128, BK=32, 8 warps (4m x 2n), warp tile 16x64, mma.m16n8k16.
// B: cp.async double-buffered (2 stages).  A: register-prefetched LDG,
// fp32->bf16 hi/lo split at STS time (single-stage smem).
// ---------------------------------------------------------------------------
__global__ __launch_bounds__(256, 2) void gemm_ln_kernel(
    const float* __restrict__ x,
    const float* __restrict__ gamma, const float* __restrict__ beta,
    float* __restrict__ out, int n_nodes)
{
    __shared__ __align__(16) __nv_bfloat16 sAh[BM * LDA];   // 5120 B
    __shared__ __align__(16) __nv_bfloat16 sAl[BM * LDA];   // 5120 B
    __shared__ __align__(16) char sB[2 * 2 * 8192];         // [stage][hi/lo][128][32] 32768 B
    __shared__ float sRed[BM * 4];                          // 1024 B

    const int tid   = threadIdx.x;
    const int warp  = tid >> 5;
    const int lane  = tid & 31;
    const int g     = lane >> 2;          // 0..7
    const int q     = lane & 3;           // 0..3
    const int warpM = warp & 3;           // rows warpM*16
    const int warpN = warp >> 2;          // cols warpN*64
    const int n0    = blockIdx.x * BM;

    // A loader coords (2 float4 per thread per tile)
    const int arow0 = tid >> 3;            // rows 0..31  (it=0)
    const int arow1 = (tid + 256) >> 3;    // rows 32..63 (it=1)
    const int akq   = tid & 7;             // float4 index in row

    float acc[8][4];
    #pragma unroll
    for (int ni = 0; ni < 8; ni++)
        #pragma unroll
        for (int c = 0; c < 4; c++) acc[ni][c] = 0.f;

    float4 aPre[2];

    // ---- A global load for tile kt into registers ----
    auto loadA = [&](int kt, float4* dstv) {
        const int k0 = kt * BK;
        #pragma unroll
        for (int it = 0; it < 2; it++) {
            int row = it == 0 ? arow0 : arow1;
            int n = n0 + row;
            float4 v = make_float4(0.f, 0.f, 0.f, 0.f);
            if (n < n_nodes) {
                if (k0 < KT) {
                    v = reinterpret_cast<const float4*>(
                            g_sums + (size_t)n * KT + k0)[akq];
                    int c = g_cnt[n * T_TYPES + (k0 >> 7)];
                    float s = 1.f / fmaxf((float)c, 1.f);
                    v.x *= s; v.y *= s; v.z *= s; v.w *= s;
                } else {
                    v = reinterpret_cast<const float4*>(
                            x + (size_t)n * D_DIM + (k0 - KT))[akq];
                }
            }
            dstv[it] = v;
        }
    };

    // ---- B cp.async for tile kt into stage ----
    auto loadB = [&](int kt) {
        const int k0 = kt * BK;
        char* stageBase = sB + (kt & 1) * 16384;
        #pragma unroll
        for (int it = 0; it < 2; it++) {
            int idx = tid + it * 256;     // 0..511
            int n = idx >> 2;
            int j = idx & 3;
            uint32_t doff = (uint32_t)(n * 64 + ((j ^ ((n >> 1) & 3)) << 4));
            cp_async16(stageBase + doff,          g_Bh + (size_t)n * KDIM + k0 + j * 8);
            cp_async16(stageBase + 8192 + doff,   g_Bl + (size_t)n * KDIM + k0 + j * 8);
        }
        CP_COMMIT();
    };

    // prologue
    loadA(0, aPre);
    loadB(0);

    for (int kt = 0; kt < KDIM / BK; kt++) {
        // STS A (sA free: all warps synced after previous compute)
        #pragma unroll
        for (int it = 0; it < 2; it++) {
            int row = it == 0 ? arow0 : arow1;
            float4 v = aPre[it];
            __nv_bfloat16 h0 = __float2bfloat16(v.x);
            __nv_bfloat16 h1 = __float2bfloat16(v.y);
            __nv_bfloat16 h2 = __float2bfloat16(v.z);
            __nv_bfloat16 h3 = __float2bfloat16(v.w);
            __nv_bfloat16 l0 = __float2bfloat16(v.x - __bfloat162float(h0));
            __nv_bfloat16 l1 = __float2bfloat16(v.y - __bfloat162float(h1));
            __nv_bfloat16 l2 = __float2bfloat16(v.z - __bfloat162float(h2));
            __nv_bfloat16 l3 = __float2bfloat16(v.w - __bfloat162float(h3));
            int off = row * LDA + akq * 4;
            *reinterpret_cast<__nv_bfloat162*>(&sAh[off])     = __nv_bfloat162(h0, h1);
            *reinterpret_cast<__nv_bfloat162*>(&sAh[off + 2]) = __nv_bfloat162(h2, h3);
            *reinterpret_cast<__nv_bfloat162*>(&sAl[off])     = __nv_bfloat162(l0, l1);
            *reinterpret_cast<__nv_bfloat162*>(&sAl[off + 2]) = __nv_bfloat162(l2, l3);
        }
        // prefetch next tile
        if (kt + 1 < KDIM / BK) {
            loadA(kt + 1, aPre);
            loadB(kt + 1);
            CP_WAIT(1);           // tile kt's B group complete
        } else {
            CP_WAIT(0);
        }
        __syncthreads();

        const char* bh = sB + (kt & 1) * 16384;
        const char* bl = bh + 8192;

        #pragma unroll
        for (int ks = 0; ks < 2; ks++) {
            const int kb = ks * 16 + q * 2;
            const int r = warpM * 16 + g;
            uint32_t ah[4], al[4];
            ah[0] = *reinterpret_cast<const uint32_t*>(&sAh[r * LDA + kb]);
            ah[1] = *reinterpret_cast<const uint32_t*>(&sAh[(r + 8) * LDA + kb]);
            ah[2] = *reinterpret_cast<const uint32_t*>(&sAh[r * LDA + kb + 8]);
            ah[3] = *reinterpret_cast<const uint32_t*>(&sAh[(r + 8) * LDA + kb + 8]);
            al[0] = *reinterpret_cast<const uint32_t*>(&sAl[r * LDA + kb]);
            al[1] = *reinterpret_cast<const uint32_t*>(&sAl[(r + 8) * LDA + kb]);
            al[2] = *reinterpret_cast<const uint32_t*>(&sAl[r * LDA + kb + 8]);
            al[3] = *reinterpret_cast<const uint32_t*>(&sAl[(r + 8) * LDA + kb + 8]);
            #pragma unroll
            for (int ni = 0; ni < 8; ni++) {
                int n = warpN * 64 + ni * 8 + g;
                uint32_t bh0 = *reinterpret_cast<const uint32_t*>(bh + bofs(n, kb));
                uint32_t bh1 = *reinterpret_cast<const uint32_t*>(bh + bofs(n, kb + 8));
                uint32_t bl0 = *reinterpret_cast<const uint32_t*>(bl + bofs(n, kb));
                uint32_t bl1 = *reinterpret_cast<const uint32_t*>(bl + bofs(n, kb + 8));
                mma16816(acc[ni], ah, bh0, bh1);
                mma16816(acc[ni], ah, bl0, bl1);
                mma16816(acc[ni], al, bh0, bh1);
            }
        }
        __syncthreads();
    }

    // ---- bias ----
    float2 bias2[8], gam2[8], bet2[8];
    #pragma unroll
    for (int ni = 0; ni < 8; ni++) {
        int col = warpN * 64 + ni * 8 + q * 2;
        bias2[ni] = *reinterpret_cast<const float2*>(&g_bias[col]);
        gam2[ni]  = *reinterpret_cast<const float2*>(&gamma[col]);
        bet2[ni]  = *reinterpret_cast<const float2*>(&beta[col]);
    }
    #pragma unroll
    for (int ni = 0; ni < 8; ni++) {
        acc[ni][0] += bias2[ni].x;
        acc[ni][1] += bias2[ni].y;
        acc[ni][2] += bias2[ni].x;
        acc[ni][3] += bias2[ni].y;
    }

    // ---- per-row partial sums over this warp's 64 cols ----
    #pragma unroll
    for (int h = 0; h < 2; h++) {
        float s = 0.f, sq = 0.f;
        #pragma unroll
        for (int ni = 0; ni < 8; ni++) {
            float v0 = acc[ni][h * 2], v1 = acc[ni][h * 2 + 1];
            s  += v0 + v1;
            sq += v0 * v0 + v1 * v1;
        }
        s  += __shfl_xor_sync(0xffffffffu, s, 1);
        s  += __shfl_xor_sync(0xffffffffu, s, 2);
        sq += __shfl_xor_sync(0xffffffffu, sq, 1);
        sq += __shfl_xor_sync(0xffffffffu, sq, 2);
        if (q == 0) {
            int r = warpM * 16 + g + h * 8;
            sRed[r * 4 + warpN]     = s;
            sRed[r * 4 + 2 + warpN] = sq;
        }
    }
    __syncthreads();

    // ---- LN + ReLU + store ----
    #pragma unroll
    for (int h = 0; h < 2; h++) {
        int r = warpM * 16 + g + h * 8;
        int n = n0 + r;
        float S  = sRed[r * 4]     + sRed[r * 4 + 1];
        float Q  = sRed[r * 4 + 2] + sRed[r * 4 + 3];
        float mean = S * (1.f / 128.f);
        float var  = Q * (1.f / 128.f) - mean * mean;
        float rstd = rsqrtf(var + LN_EPS);
        if (n < n_nodes) {
            #pragma unroll
            for (int ni = 0; ni < 8; ni++) {
                int col = warpN * 64 + ni * 8 + q * 2;
                float v0 = acc[ni][h * 2], v1 = acc[ni][h * 2 + 1];
                float y0 = fmaxf((v0 - mean) * rstd * gam2[ni].x + bet2[ni].x, 0.f);
                float y1 = fmaxf((v1 - mean) * rstd * gam2[ni].y + bet2[ni].y, 0.f);
                *reinterpret_cast<float2*>(&out[(size_t)n * D_DIM + col]) =
                    make_float2(y0, y1);
            }
        }
    }
}

// ---------------------------------------------------------------------------
extern "C" void kernel_launch(void* const* d_in, const int* in_sizes, int n_in,
                              void* d_out, int out_size) {
    const float* x     = (const float*)d_in[0];
    const int*   ei    = (const int*)d_in[1];   // int32 (JAX x64 off)
    const int*   et    = (const int*)d_in[2];   // int32
    const float* Wl    = (const float*)d_in[3];
    const float* Wr    = (const float*)d_in[4];
    const float* b     = (const float*)d_in[5];
    const float* emb   = (const float*)d_in[6];
    const float* gamma = (const float*)d_in[7];
    const float* beta  = (const float*)d_in[8];
    float* out = (float*)d_out;

    int n_nodes = in_sizes[0] / D_DIM;
    int E       = in_sizes[2];

    zero_kernel<<<2048, 256>>>(n_nodes);
    prep_b_kernel<<<(D_DIM * KDIM + 255) / 256, 256>>>(Wl, Wr, b, emb);
    scatter_kernel<<<(E + 7) / 8, 256>>>(x, ei, et, E);
    gemm_ln_kernel<<<(n_nodes + BM - 1) / BM, 256>>>(x, gamma, beta, out, n_nodes);
}